// round 5
// baseline (speedup 1.0000x reference)
#include <cuda_runtime.h>
#include <math.h>

#define BQ 64
#define NQ 2048
#define DQ 256
#define HQ 8
#define KDQ 32
#define VDQ 32
#define OQ 256
#define HV 256   // H * VD = flattened gate dim

// ---------------- scratch (static device arrays: no allocation) ----------------
__device__ float g_q[BQ * HQ * KDQ];                 // [B][H][KD] = [B][256]
__device__ float g_v[(size_t)BQ * NQ * VDQ];         // [B][N][VD]  16 MB
__device__ float g_logits[(size_t)BQ * HQ * NQ];     // [B][H][N]    4 MB
__device__ float g_wavg[BQ * HV];                    // [B][H*VD]

// ---------------- tf32 helpers --------------------------------------------------
__device__ __forceinline__ unsigned f2tf(float f) {
    unsigned u;
    asm("cvt.rna.tf32.f32 %0, %1;" : "=r"(u) : "f"(f));
    return u;
}

__device__ __forceinline__ void mma_tf32(float* d, const unsigned* a, const unsigned* b) {
    asm volatile(
        "mma.sync.aligned.m16n8k8.row.col.f32.tf32.tf32.f32 "
        "{%0,%1,%2,%3}, {%4,%5,%6,%7}, {%8,%9}, {%0,%1,%2,%3};\n"
        : "+f"(d[0]), "+f"(d[1]), "+f"(d[2]), "+f"(d[3])
        : "r"(a[0]), "r"(a[1]), "r"(a[2]), "r"(a[3]), "r"(b[0]), "r"(b[1]));
}

// ---------------- K1: masked mean over N, then q = q_avg @ query_w * kd^-0.5 ----
__global__ void k1_qavg(const float* __restrict__ qd, const float* __restrict__ qm,
                        const float* __restrict__ qw) {
    int b = blockIdx.x, t = threadIdx.x;
    __shared__ float red[256];
    __shared__ float qavg[DQ];

    float ms = 0.f;
    for (int n = t; n < NQ; n += 256) ms += qm[b * NQ + n];
    red[t] = ms;
    __syncthreads();
    for (int s = 128; s > 0; s >>= 1) {
        if (t < s) red[t] += red[t + s];
        __syncthreads();
    }
    float masksum = red[0] + 1e-10f;

    const float* qdb = qd + (size_t)b * NQ * DQ + t;
    const float* qmb = qm + b * NQ;
    float acc = 0.f;
#pragma unroll 8
    for (int n = 0; n < NQ; n++) acc += qmb[n] * qdb[(size_t)n * DQ];
    qavg[t] = acc / masksum;
    __syncthreads();

    float r = 0.f;
#pragma unroll 8
    for (int d = 0; d < DQ; d++) r += qavg[d] * qw[d * 256 + t];
    g_q[b * 256 + t] = r * 0.17677669529663687f;  // 32^-0.5
}

// ---------------- K2: k = m@key_w, v = m@value_w, logits = q.k + bias ----------
__global__ void k2_kv_logits(const float* __restrict__ md, const float* __restrict__ qm,
                             const float* __restrict__ kw, const float* __restrict__ vw) {
    int n0 = blockIdx.x * 128;
    int b  = blockIdx.y;
    int t  = threadIdx.x;
    int tc = t & 15, tr = t >> 4;

    __shared__ float As[128][33];   // A tile, later reused for k values
    __shared__ float Ws[32][65];    // weight K-chunk
    __shared__ float qs[8][32];

    float acc[8][4];
#pragma unroll
    for (int i = 0; i < 8; i++)
#pragma unroll
        for (int j = 0; j < 4; j++) acc[i][j] = 0.f;

    const float* Abase = md + ((size_t)b * NQ + n0) * DQ;

    for (int kc = 0; kc < 8; kc++) {
#pragma unroll
        for (int i = 0; i < 4; i++) {
            int id = t + i * 256;
            int row = id >> 3, f4 = id & 7;
            float4 v4 = *(const float4*)(Abase + (size_t)row * DQ + kc * 32 + f4 * 4);
            As[row][f4 * 4 + 0] = v4.x; As[row][f4 * 4 + 1] = v4.y;
            As[row][f4 * 4 + 2] = v4.z; As[row][f4 * 4 + 3] = v4.w;
        }
#pragma unroll
        for (int i = 0; i < 8; i++) {
            int id = t + i * 256;
            int kk = id >> 6, c = id & 63;
            Ws[kk][c] = (c < 32) ? kw[(kc * 32 + kk) * 32 + c]
                                 : vw[(kc * 32 + kk) * 32 + (c - 32)];
        }
        __syncthreads();
#pragma unroll
        for (int kk = 0; kk < 32; kk++) {
            float bv[4];
#pragma unroll
            for (int j = 0; j < 4; j++) bv[j] = Ws[kk][tc * 4 + j];
#pragma unroll
            for (int i = 0; i < 8; i++) {
                float a = As[tr * 8 + i][kk];
#pragma unroll
                for (int j = 0; j < 4; j++) acc[i][j] += a * bv[j];
            }
        }
        __syncthreads();
    }

    qs[t >> 5][t & 31] = g_q[b * 256 + t];

#pragma unroll
    for (int i = 0; i < 8; i++) {
        int row = tr * 8 + i;
#pragma unroll
        for (int j = 0; j < 4; j++) {
            int c = tc * 4 + j;
            if (c < 32) As[row][c] = acc[i][j];
            else        g_v[((size_t)b * NQ + n0 + row) * VDQ + (c - 32)] = acc[i][j];
        }
    }
    __syncthreads();

#pragma unroll
    for (int ii = 0; ii < 4; ii++) {
        int idx = ii * 256 + t;
        int h = idx & 7, n = idx >> 3;
        float s = 0.f;
#pragma unroll
        for (int kd = 0; kd < 32; kd++) s += qs[h][kd] * As[n][kd];
        float maskv = qm[b * NQ + n0 + n];
        g_logits[((size_t)b * HQ + h) * NQ + n0 + n] = s + 1e9f * (maskv - 1.0f);
    }
}

// ---------------- K3: softmax over N + weighted_avg (single pass over v) --------
__global__ void k3_softmax_wavg() {
    int b = blockIdx.x, t = threadIdx.x;
    int lane = t & 31, wid = t >> 5;
    __shared__ float mxs[8], invS[8];
    __shared__ float vsm[128][33];
    __shared__ float lgs[8][128];

    {
        const float* lrow = g_logits + ((size_t)b * HQ + wid) * NQ;
        float m = -1e30f;
        for (int n = lane; n < NQ; n += 32) m = fmaxf(m, lrow[n]);
#pragma unroll
        for (int o = 16; o > 0; o >>= 1) m = fmaxf(m, __shfl_xor_sync(0xffffffffu, m, o));
        float s = 0.f;
        for (int n = lane; n < NQ; n += 32) s += __expf(lrow[n] - m);
#pragma unroll
        for (int o = 16; o > 0; o >>= 1) s += __shfl_xor_sync(0xffffffffu, s, o);
        if (lane == 0) { mxs[wid] = m; invS[wid] = 1.0f / s; }
    }
    __syncthreads();

    int h = wid, vd = lane;
    float acc = 0.f;

    for (int c = 0; c < NQ / 128; c++) {
#pragma unroll
        for (int i = 0; i < 16; i++) {
            int s = t + i * 256;
            int row = s >> 5, col = s & 31;
            vsm[row][col] = g_v[((size_t)b * NQ + c * 128 + row) * VDQ + col];
        }
#pragma unroll
        for (int i = 0; i < 4; i++) {
            int s = t + i * 256;
            int hh = s >> 7, n = s & 127;
            lgs[hh][n] = g_logits[((size_t)b * HQ + hh) * NQ + c * 128 + n];
        }
        __syncthreads();
#pragma unroll
        for (int i = 0; i < 4; i++) {
            int s = t + i * 256;
            int hh = s >> 7, n = s & 127;
            lgs[hh][n] = __expf(lgs[hh][n] - mxs[hh]);
        }
        __syncthreads();
#pragma unroll 8
        for (int n = 0; n < 128; n++)
            acc += lgs[h][n] * vsm[n][vd];
        __syncthreads();
    }
    g_wavg[b * HV + h * 32 + vd] = acc * invS[h];
}

// ---------------- K4 fused: gate GEMM + sigmoid*wavg -> G(smem) -> output GEMM --
// smem layout (unsigned words):
//   As [128][36]  @ 0        (4608)
//   Bs [32][132]  @ 4608     (4224)
//   G  [128][260] @ 8832     (33280)   total 42112 words = 168448 B
#define AS_OFF 0
#define BS_OFF 4608
#define G_OFF  8832
#define SMEM_WORDS 42112

__global__ __launch_bounds__(256) void k4_fused(const float* __restrict__ qd,
                                                const float* __restrict__ gw,
                                                const float* __restrict__ gb,
                                                const float* __restrict__ ow,
                                                const float* __restrict__ ob,
                                                float* __restrict__ out) {
    extern __shared__ unsigned sm[];
    unsigned* As = sm + AS_OFF;
    unsigned* Bs = sm + BS_OFF;
    unsigned* G  = sm + G_OFF;

    const int r0 = blockIdx.x * 128;
    const int b  = r0 >> 11;               // 2048 rows per batch
    const int t = threadIdx.x;
    const int lane = t & 31, wid = t >> 5;
    const int wm = wid >> 1, wn = wid & 1;  // 4 x 2 warp grid
    const int gr = lane >> 2, tig = lane & 3;

    // load indices (shared by A and B tile movers)
    const int arow = (t * 4 + 0) >> 3 >= 0 ? 0 : 0; // dummy to quiet compiler
    (void)arow;

    float acc[2][8][4];

    // ================= PHASE A: G = sigmoid(qd @ gw + gb) * wavg ================
    const float* Abase = qd + (size_t)r0 * DQ;

#pragma unroll 1
    for (int chalf = 0; chalf < 2; chalf++) {
        const int c0 = chalf * 128;
#pragma unroll
        for (int mi = 0; mi < 2; mi++)
#pragma unroll
            for (int ni = 0; ni < 8; ni++)
#pragma unroll
                for (int j = 0; j < 4; j++) acc[mi][ni][j] = 0.f;

        float4 a4[4], b4[4];
        // prefetch kc = 0
#pragma unroll
        for (int i = 0; i < 4; i++) {
            int s = t + i * 256;
            int row = s >> 3, c4 = s & 7;
            a4[i] = *(const float4*)(Abase + (size_t)row * DQ + c4 * 4);
            int k = s >> 5, n4 = s & 31;
            b4[i] = *(const float4*)(gw + (size_t)k * HV + c0 + n4 * 4);
        }

#pragma unroll 1
        for (int kc = 0; kc < 8; kc++) {
            __syncthreads();   // previous MMA reads of As/Bs done
#pragma unroll
            for (int i = 0; i < 4; i++) {
                int s = t + i * 256;
                int row = s >> 3, c4 = s & 7;
                As[row * 36 + c4 * 4 + 0] = f2tf(a4[i].x);
                As[row * 36 + c4 * 4 + 1] = f2tf(a4[i].y);
                As[row * 36 + c4 * 4 + 2] = f2tf(a4[i].z);
                As[row * 36 + c4 * 4 + 3] = f2tf(a4[i].w);
                int k = s >> 5, n4 = s & 31;
                Bs[k * 132 + n4 * 4 + 0] = f2tf(b4[i].x);
                Bs[k * 132 + n4 * 4 + 1] = f2tf(b4[i].y);
                Bs[k * 132 + n4 * 4 + 2] = f2tf(b4[i].z);
                Bs[k * 132 + n4 * 4 + 3] = f2tf(b4[i].w);
            }
            __syncthreads();
            if (kc < 7) {   // prefetch next chunk while MMA runs
#pragma unroll
                for (int i = 0; i < 4; i++) {
                    int s = t + i * 256;
                    int row = s >> 3, c4 = s & 7;
                    a4[i] = *(const float4*)(Abase + (size_t)row * DQ + (kc + 1) * 32 + c4 * 4);
                    int k = s >> 5, n4 = s & 31;
                    b4[i] = *(const float4*)(gw + (size_t)((kc + 1) * 32 + k) * HV + c0 + n4 * 4);
                }
            }
#pragma unroll
            for (int ks = 0; ks < 4; ks++) {
                const int k0 = ks * 8;
                unsigned af[2][4];
#pragma unroll
                for (int mi = 0; mi < 2; mi++) {
                    int rb = wm * 32 + mi * 16;
                    af[mi][0] = As[(rb + gr) * 36 + k0 + tig];
                    af[mi][1] = As[(rb + gr + 8) * 36 + k0 + tig];
                    af[mi][2] = As[(rb + gr) * 36 + k0 + tig + 4];
                    af[mi][3] = As[(rb + gr + 8) * 36 + k0 + tig + 4];
                }
                unsigned bf[8][2];
#pragma unroll
                for (int ni = 0; ni < 8; ni++) {
                    int cb = wn * 64 + ni * 8 + gr;
                    bf[ni][0] = Bs[(k0 + tig) * 132 + cb];
                    bf[ni][1] = Bs[(k0 + tig + 4) * 132 + cb];
                }
#pragma unroll
                for (int mi = 0; mi < 2; mi++)
#pragma unroll
                    for (int ni = 0; ni < 8; ni++)
                        mma_tf32(acc[mi][ni], af[mi], bf[ni]);
            }
        }

        // epilogue A: gate -> G (tf32 in smem)
#pragma unroll
        for (int mi = 0; mi < 2; mi++) {
#pragma unroll
            for (int ni = 0; ni < 8; ni++) {
                int row = wm * 32 + mi * 16 + gr;
                int col = c0 + wn * 64 + ni * 8 + tig * 2;
#pragma unroll
                for (int half = 0; half < 2; half++) {
                    int rr = row + half * 8;
                    float x0 = acc[mi][ni][half * 2 + 0] + gb[col];
                    float x1 = acc[mi][ni][half * 2 + 1] + gb[col + 1];
                    float g0 = 1.0f / (1.0f + __expf(-x0));
                    float g1 = 1.0f / (1.0f + __expf(-x1));
                    float2 w = *(const float2*)&g_wavg[b * HV + col];
                    G[rr * 260 + col]     = f2tf(g0 * w.x);
                    G[rr * 260 + col + 1] = f2tf(g1 * w.y);
                }
            }
        }
    }

    // ================= PHASE B: out = G @ ow + ob ================================
#pragma unroll 1
    for (int chalf = 0; chalf < 2; chalf++) {
        const int c0 = chalf * 128;
#pragma unroll
        for (int mi = 0; mi < 2; mi++)
#pragma unroll
            for (int ni = 0; ni < 8; ni++)
#pragma unroll
                for (int j = 0; j < 4; j++) acc[mi][ni][j] = 0.f;

        float4 b4[4];
#pragma unroll
        for (int i = 0; i < 4; i++) {
            int s = t + i * 256;
            int k = s >> 5, n4 = s & 31;
            b4[i] = *(const float4*)(ow + (size_t)k * OQ + c0 + n4 * 4);
        }

#pragma unroll 1
        for (int kc = 0; kc < 8; kc++) {
            __syncthreads();   // also orders G writes (first iter) / Bs reads
#pragma unroll
            for (int i = 0; i < 4; i++) {
                int s = t + i * 256;
                int k = s >> 5, n4 = s & 31;
                Bs[k * 132 + n4 * 4 + 0] = f2tf(b4[i].x);
                Bs[k * 132 + n4 * 4 + 1] = f2tf(b4[i].y);
                Bs[k * 132 + n4 * 4 + 2] = f2tf(b4[i].z);
                Bs[k * 132 + n4 * 4 + 3] = f2tf(b4[i].w);
            }
            __syncthreads();
            if (kc < 7) {
#pragma unroll
                for (int i = 0; i < 4; i++) {
                    int s = t + i * 256;
                    int k = s >> 5, n4 = s & 31;
                    b4[i] = *(const float4*)(ow + (size_t)((kc + 1) * 32 + k) * OQ + c0 + n4 * 4);
                }
            }
#pragma unroll
            for (int ks = 0; ks < 4; ks++) {
                const int k0 = kc * 32 + ks * 8;
                unsigned af[2][4];
#pragma unroll
                for (int mi = 0; mi < 2; mi++) {
                    int rb = wm * 32 + mi * 16;
                    af[mi][0] = G[(rb + gr) * 260 + k0 + tig];
                    af[mi][1] = G[(rb + gr + 8) * 260 + k0 + tig];
                    af[mi][2] = G[(rb + gr) * 260 + k0 + tig + 4];
                    af[mi][3] = G[(rb + gr + 8) * 260 + k0 + tig + 4];
                }
                const int kk0 = ks * 8;
                unsigned bf[8][2];
#pragma unroll
                for (int ni = 0; ni < 8; ni++) {
                    int cb = wn * 64 + ni * 8 + gr;
                    bf[ni][0] = Bs[(kk0 + tig) * 132 + cb];
                    bf[ni][1] = Bs[(kk0 + tig + 4) * 132 + cb];
                }
#pragma unroll
                for (int mi = 0; mi < 2; mi++)
#pragma unroll
                    for (int ni = 0; ni < 8; ni++)
                        mma_tf32(acc[mi][ni], af[mi], bf[ni]);
            }
        }

        // epilogue B
#pragma unroll
        for (int mi = 0; mi < 2; mi++) {
#pragma unroll
            for (int ni = 0; ni < 8; ni++) {
                int row = r0 + wm * 32 + mi * 16 + gr;
                int col = c0 + wn * 64 + ni * 8 + tig * 2;
#pragma unroll
                for (int half = 0; half < 2; half++) {
                    int rr = row + half * 8;
                    float2 o;
                    o.x = acc[mi][ni][half * 2 + 0] + ob[col];
                    o.y = acc[mi][ni][half * 2 + 1] + ob[col + 1];
                    *(float2*)&out[(size_t)rr * OQ + col] = o;
                }
            }
        }
    }
}

// ---------------- launcher ------------------------------------------------------
extern "C" void kernel_launch(void* const* d_in, const int* in_sizes, int n_in,
                              void* d_out, int out_size) {
    const float* qd = (const float*)d_in[0];  // q_data  [B,N,D]
    const float* md = (const float*)d_in[1];  // m_data  [B,N,D]
    const float* qm = (const float*)d_in[2];  // q_mask  [B,N,1]
    const float* qw = (const float*)d_in[3];  // query_w [D,H,KD]
    const float* kw = (const float*)d_in[4];  // key_w   [D,KD]
    const float* vw = (const float*)d_in[5];  // value_w [D,VD]
    const float* gw = (const float*)d_in[6];  // gating_w [D,H,VD]
    const float* gb = (const float*)d_in[7];  // gating_b [H,VD]
    const float* ow = (const float*)d_in[8];  // output_w [H,VD,O]
    const float* ob = (const float*)d_in[9];  // output_b [O]
    float* out = (float*)d_out;               // [B,N,O] fp32

    static bool smem_set = false;
    cudaFuncSetAttribute(k4_fused, cudaFuncAttributeMaxDynamicSharedMemorySize,
                         SMEM_WORDS * 4);
    (void)smem_set;

    k1_qavg<<<BQ, 256>>>(qd, qm, qw);
    k2_kv_logits<<<dim3(NQ / 128, BQ), 256>>>(md, qm, kw, vw);
    k3_softmax_wavg<<<BQ, 256>>>();
    k4_fused<<<(BQ * NQ) / 128, 256, SMEM_WORDS * 4>>>(qd, gw, gb, ow, ob, out);
}

// round 7
// speedup vs baseline: 1.2526x; 1.2526x over previous
#include <cuda_runtime.h>
#include <math.h>
#include <stdint.h>

#define BQ 64
#define NQ 2048
#define DQ 256
#define HQ 8
#define KDQ 32
#define VDQ 32
#define OQ 256
#define HV 256

// ---------------- scratch (static device arrays: no allocation) ----------------
__device__ float g_q[BQ * HQ * KDQ];
__device__ float g_v[(size_t)BQ * NQ * VDQ];         // 16 MB
__device__ float g_logits[(size_t)BQ * HQ * NQ];     // 4 MB
__device__ float g_wavg[BQ * HV];
__device__ float g_gated[(size_t)BQ * NQ * HV];      // 128 MB (tf32 patterns)
__device__ float g_gwtf[DQ * HV];                    // weights as tf32 patterns
__device__ float g_owtf[HV * OQ];

// ---------------- helpers -------------------------------------------------------
__device__ __forceinline__ unsigned f2tf(float f) {
    unsigned u;
    asm("cvt.rna.tf32.f32 %0, %1;" : "=r"(u) : "f"(f));
    return u;
}
__device__ __forceinline__ uint32_t smem_u32(const void* p) {
    uint32_t a;
    asm("{ .reg .u64 t; cvta.to.shared.u64 t, %1; cvt.u32.u64 %0, t; }" : "=r"(a) : "l"(p));
    return a;
}
__device__ __forceinline__ void cp16(uint32_t saddr, const void* g) {
    asm volatile("cp.async.cg.shared.global [%0], [%1], 16;" :: "r"(saddr), "l"(g) : "memory");
}
__device__ __forceinline__ void cp_commit() {
    asm volatile("cp.async.commit_group;" ::: "memory");
}
template <int N>
__device__ __forceinline__ void cp_wait() {
    asm volatile("cp.async.wait_group %0;" :: "n"(N) : "memory");
}
__device__ __forceinline__ void mma_tf32(float* d, const unsigned* a, const unsigned* b) {
    asm volatile(
        "mma.sync.aligned.m16n8k8.row.col.f32.tf32.tf32.f32 "
        "{%0,%1,%2,%3}, {%4,%5,%6,%7}, {%8,%9}, {%0,%1,%2,%3};\n"
        : "+f"(d[0]), "+f"(d[1]), "+f"(d[2]), "+f"(d[3])
        : "r"(a[0]), "r"(a[1]), "r"(a[2]), "r"(a[3]), "r"(b[0]), "r"(b[1]));
}

// ---------------- K0: weights -> tf32 patterns ----------------------------------
__global__ void k0_cvtw(const float* __restrict__ gw, const float* __restrict__ ow) {
    int i = blockIdx.x * 256 + threadIdx.x;   // 65536
    g_gwtf[i] = __uint_as_float(f2tf(gw[i]));
    g_owtf[i] = __uint_as_float(f2tf(ow[i]));
}

// ---------------- K1 ------------------------------------------------------------
__global__ void k1_qavg(const float* __restrict__ qd, const float* __restrict__ qm,
                        const float* __restrict__ qw) {
    int b = blockIdx.x, t = threadIdx.x;
    __shared__ float red[256];
    __shared__ float qavg[DQ];

    float ms = 0.f;
    for (int n = t; n < NQ; n += 256) ms += qm[b * NQ + n];
    red[t] = ms;
    __syncthreads();
    for (int s = 128; s > 0; s >>= 1) {
        if (t < s) red[t] += red[t + s];
        __syncthreads();
    }
    float masksum = red[0] + 1e-10f;

    const float* qdb = qd + (size_t)b * NQ * DQ + t;
    const float* qmb = qm + b * NQ;
    float acc = 0.f;
#pragma unroll 8
    for (int n = 0; n < NQ; n++) acc += qmb[n] * qdb[(size_t)n * DQ];
    qavg[t] = acc / masksum;
    __syncthreads();

    float r = 0.f;
#pragma unroll 8
    for (int d = 0; d < DQ; d++) r += qavg[d] * qw[d * 256 + t];
    g_q[b * 256 + t] = r * 0.17677669529663687f;
}

// ---------------- K2: k/v via tf32 MMA + logits ---------------------------------
// tile: M=128 rows (n), N=64 cols (0-31 k | 32-63 v), K=256
__global__ __launch_bounds__(256) void k2_kv_logits(const float* __restrict__ md,
                                                    const float* __restrict__ qm,
                                                    const float* __restrict__ kw,
                                                    const float* __restrict__ vw) {
    int n0 = blockIdx.x * 128;
    int b  = blockIdx.y;
    int t  = threadIdx.x;
    const int lane = t & 31, wid = t >> 5;
    const int wm = wid >> 1, wn = wid & 1;
    const int gr = lane >> 2, tig = lane & 3;

    __shared__ unsigned As[128 * 36];
    __shared__ unsigned Bs[32 * 68];
    __shared__ float qs[8][32];
    float* Asf = (float*)As;

    float acc[2][4][4];
#pragma unroll
    for (int mi = 0; mi < 2; mi++)
#pragma unroll
        for (int ni = 0; ni < 4; ni++)
#pragma unroll
            for (int j = 0; j < 4; j++) acc[mi][ni][j] = 0.f;

    const float* Abase = md + ((size_t)b * NQ + n0) * DQ;

    float4 a4[4], b4[2];
#pragma unroll
    for (int i = 0; i < 4; i++) {
        int s = t + i * 256;
        int row = s >> 3, c4 = s & 7;
        a4[i] = *(const float4*)(Abase + (size_t)row * DQ + c4 * 4);
    }
#pragma unroll
    for (int i = 0; i < 2; i++) {
        int s = t + i * 256;
        int k = s >> 4, c8 = s & 15;
        b4[i] = (c8 < 8) ? *(const float4*)(kw + k * 32 + c8 * 4)
                         : *(const float4*)(vw + k * 32 + (c8 - 8) * 4);
    }

#pragma unroll 1
    for (int kc = 0; kc < 8; kc++) {
        __syncthreads();
#pragma unroll
        for (int i = 0; i < 4; i++) {
            int s = t + i * 256;
            int row = s >> 3, c4 = s & 7;
            As[row * 36 + c4 * 4 + 0] = f2tf(a4[i].x);
            As[row * 36 + c4 * 4 + 1] = f2tf(a4[i].y);
            As[row * 36 + c4 * 4 + 2] = f2tf(a4[i].z);
            As[row * 36 + c4 * 4 + 3] = f2tf(a4[i].w);
        }
#pragma unroll
        for (int i = 0; i < 2; i++) {
            int s = t + i * 256;
            int k = s >> 4, c8 = s & 15;
            Bs[k * 68 + c8 * 4 + 0] = f2tf(b4[i].x);
            Bs[k * 68 + c8 * 4 + 1] = f2tf(b4[i].y);
            Bs[k * 68 + c8 * 4 + 2] = f2tf(b4[i].z);
            Bs[k * 68 + c8 * 4 + 3] = f2tf(b4[i].w);
        }
        __syncthreads();
        if (kc < 7) {
#pragma unroll
            for (int i = 0; i < 4; i++) {
                int s = t + i * 256;
                int row = s >> 3, c4 = s & 7;
                a4[i] = *(const float4*)(Abase + (size_t)row * DQ + (kc + 1) * 32 + c4 * 4);
            }
#pragma unroll
            for (int i = 0; i < 2; i++) {
                int s = t + i * 256;
                int k = (kc + 1) * 32 + (s >> 4);
                int c8 = s & 15;
                b4[i] = (c8 < 8) ? *(const float4*)(kw + k * 32 + c8 * 4)
                                 : *(const float4*)(vw + k * 32 + (c8 - 8) * 4);
            }
        }
#pragma unroll
        for (int ks = 0; ks < 4; ks++) {
            const int k0 = ks * 8;
            unsigned af[2][4];
#pragma unroll
            for (int mi = 0; mi < 2; mi++) {
                int rb = wm * 32 + mi * 16;
                af[mi][0] = As[(rb + gr) * 36 + k0 + tig];
                af[mi][1] = As[(rb + gr + 8) * 36 + k0 + tig];
                af[mi][2] = As[(rb + gr) * 36 + k0 + tig + 4];
                af[mi][3] = As[(rb + gr + 8) * 36 + k0 + tig + 4];
            }
            unsigned bf[4][2];
#pragma unroll
            for (int ni = 0; ni < 4; ni++) {
                int cb = wn * 32 + ni * 8 + gr;
                bf[ni][0] = Bs[(k0 + tig) * 68 + cb];
                bf[ni][1] = Bs[(k0 + tig + 4) * 68 + cb];
            }
#pragma unroll
            for (int mi = 0; mi < 2; mi++)
#pragma unroll
                for (int ni = 0; ni < 4; ni++)
                    mma_tf32(acc[mi][ni], af[mi], bf[ni]);
        }
    }

    __syncthreads();   // all MMA reads done; reuse As as float storage
    qs[t >> 5][t & 31] = g_q[b * 256 + t];

#pragma unroll
    for (int mi = 0; mi < 2; mi++) {
#pragma unroll
        for (int ni = 0; ni < 4; ni++) {
            int col = wn * 32 + ni * 8 + tig * 2;
#pragma unroll
            for (int half = 0; half < 2; half++) {
                int row = wm * 32 + mi * 16 + gr + half * 8;
                float x0 = acc[mi][ni][half * 2 + 0];
                float x1 = acc[mi][ni][half * 2 + 1];
                if (col < 32) {
                    Asf[row * 33 + col] = x0;
                    Asf[row * 33 + col + 1] = x1;
                } else {
                    g_v[((size_t)b * NQ + n0 + row) * VDQ + (col - 32)] = x0;
                    g_v[((size_t)b * NQ + n0 + row) * VDQ + (col - 31)] = x1;
                }
            }
        }
    }
    __syncthreads();

#pragma unroll
    for (int ii = 0; ii < 4; ii++) {
        int idx = ii * 256 + t;
        int h = idx & 7, n = idx >> 3;
        float s = 0.f;
#pragma unroll
        for (int kd = 0; kd < 32; kd++) s += qs[h][kd] * Asf[n * 33 + kd];
        float maskv = qm[b * NQ + n0 + n];
        g_logits[((size_t)b * HQ + h) * NQ + n0 + n] = s + 1e9f * (maskv - 1.0f);
    }
}

// ---------------- K3 ------------------------------------------------------------
__global__ void k3_softmax_wavg() {
    int b = blockIdx.x, t = threadIdx.x;
    int lane = t & 31, wid = t >> 5;
    __shared__ float mxs[8], invS[8];
    __shared__ float vsm[128][33];
    __shared__ float lgs[8][128];

    {
        const float* lrow = g_logits + ((size_t)b * HQ + wid) * NQ;
        float m = -1e30f;
        for (int n = lane; n < NQ; n += 32) m = fmaxf(m, lrow[n]);
#pragma unroll
        for (int o = 16; o > 0; o >>= 1) m = fmaxf(m, __shfl_xor_sync(0xffffffffu, m, o));
        float s = 0.f;
        for (int n = lane; n < NQ; n += 32) s += __expf(lrow[n] - m);
#pragma unroll
        for (int o = 16; o > 0; o >>= 1) s += __shfl_xor_sync(0xffffffffu, s, o);
        if (lane == 0) { mxs[wid] = m; invS[wid] = 1.0f / s; }
    }
    __syncthreads();

    int h = wid, vd = lane;
    float acc = 0.f;

    for (int c = 0; c < NQ / 128; c++) {
#pragma unroll
        for (int i = 0; i < 16; i++) {
            int s = t + i * 256;
            int row = s >> 5, col = s & 31;
            vsm[row][col] = g_v[((size_t)b * NQ + c * 128 + row) * VDQ + col];
        }
#pragma unroll
        for (int i = 0; i < 4; i++) {
            int s = t + i * 256;
            int hh = s >> 7, n = s & 127;
            lgs[hh][n] = g_logits[((size_t)b * HQ + hh) * NQ + c * 128 + n];
        }
        __syncthreads();
#pragma unroll
        for (int i = 0; i < 4; i++) {
            int s = t + i * 256;
            int hh = s >> 7, n = s & 127;
            lgs[hh][n] = __expf(lgs[hh][n] - mxs[hh]);
        }
        __syncthreads();
#pragma unroll 8
        for (int n = 0; n < 128; n++)
            acc += lgs[h][n] * vsm[n][vd];
        __syncthreads();
    }
    g_wavg[b * HV + h * 32 + vd] = acc * invS[h];
}

// ---------------- K4: tf32 MMA, cp.async double-buffered -------------------------
// stage (words): A[128][36]=4608  B[32][132]=4224  -> 8832 words = 35328 B
// two stages: 70656 B dynamic smem; 2 CTAs/SM.
#define ST_WORDS 8832
#define ST_BYTES 35328
#define B_WOFF   4608
#define B_BOFF   18432
#define K4_SMEM  (2 * ST_BYTES)

// EPI = 0: A raw fp32 (qd), cvt in-kernel; epilogue gate -> g_gated (tf32 patterns)
// EPI = 1: A pre-converted (g_gated) via cp.async; epilogue +bias -> out
template <int EPI>
__global__ __launch_bounds__(256, 2) void k4_mma(const float* __restrict__ Ag,
                                                 const float* __restrict__ Bg,
                                                 const float* __restrict__ bias,
                                                 float* __restrict__ Cg) {
    extern __shared__ unsigned sm[];
    const uint32_t sb = smem_u32(sm);

    const int r0 = blockIdx.x * 128;
    const int c0 = blockIdx.y * 128;
    const int t = threadIdx.x;
    const int lane = t & 31, wid = t >> 5;
    const int wm = wid >> 1, wn = wid & 1;
    const int gr = lane >> 2, tig = lane & 3;
    const int b = r0 >> 11;

    float acc[2][8][4];
#pragma unroll
    for (int mi = 0; mi < 2; mi++)
#pragma unroll
        for (int ni = 0; ni < 8; ni++)
#pragma unroll
            for (int j = 0; j < 4; j++) acc[mi][ni][j] = 0.f;

    // per-thread copy coordinates
    const int arow = t >> 1, ac4 = (t & 1) * 4;      // unused helper (kept simple below)
    (void)arow; (void)ac4;

    float4 a4[4];

    // ---- prologue: stage 0 ----
    {
        uint32_t base = sb;
#pragma unroll
        for (int i = 0; i < 4; i++) {     // B tile
            int s = t + i * 256;
            int k = s >> 5, n4 = s & 31;
            cp16(base + B_BOFF + (uint32_t)k * 528 + n4 * 16,
                 Bg + (size_t)k * 256 + c0 + n4 * 4);
        }
        if (EPI == 1) {
#pragma unroll
            for (int i = 0; i < 4; i++) { // A tile via cp.async
                int s = t + i * 256;
                int row = s >> 3, c4 = s & 7;
                cp16(base + (uint32_t)row * 144 + c4 * 16,
                     Ag + (size_t)(r0 + row) * 256 + c4 * 4);
            }
        }
        cp_commit();
        if (EPI == 0) {
#pragma unroll
            for (int i = 0; i < 4; i++) {
                int s = t + i * 256;
                int row = s >> 3, c4 = s & 7;
                a4[i] = *(const float4*)(Ag + (size_t)(r0 + row) * 256 + c4 * 4);
            }
        }
    }

#pragma unroll 1
    for (int kc = 0; kc < 8; kc++) {
        const int st = kc & 1;
        unsigned* As = sm + st * ST_WORDS;
        unsigned* Bs = As + B_WOFF;

        if (EPI == 0) {
            // STS current A chunk (cvt), prefetch next into regs
#pragma unroll
            for (int i = 0; i < 4; i++) {
                int s = t + i * 256;
                int row = s >> 3, c4 = s & 7;
                uint4 w;
                w.x = f2tf(a4[i].x); w.y = f2tf(a4[i].y);
                w.z = f2tf(a4[i].z); w.w = f2tf(a4[i].w);
                *(uint4*)((unsigned char*)As + (uint32_t)row * 144 + c4 * 16) = w;
            }
            if (kc < 7) {
#pragma unroll
                for (int i = 0; i < 4; i++) {
                    int s = t + i * 256;
                    int row = s >> 3, c4 = s & 7;
                    a4[i] = *(const float4*)(Ag + (size_t)(r0 + row) * 256 + (kc + 1) * 32 + c4 * 4);
                }
            }
        }

        if (kc < 7) {
            // issue stage kc+1 into other buffer
            uint32_t base = sb + ((kc + 1) & 1) * ST_BYTES;
#pragma unroll
            for (int i = 0; i < 4; i++) {
                int s = t + i * 256;
                int k = s >> 5, n4 = s & 31;
                cp16(base + B_BOFF + (uint32_t)k * 528 + n4 * 16,
                     Bg + (size_t)((kc + 1) * 32 + k) * 256 + c0 + n4 * 4);
            }
            if (EPI == 1) {
#pragma unroll
                for (int i = 0; i < 4; i++) {
                    int s = t + i * 256;
                    int row = s >> 3, c4 = s & 7;
                    cp16(base + (uint32_t)row * 144 + c4 * 16,
                         Ag + (size_t)(r0 + row) * 256 + (kc + 1) * 32 + c4 * 4);
                }
            }
            cp_commit();
            cp_wait<1>();
        } else {
            cp_wait<0>();
        }
        __syncthreads();

        // ---- compute on stage st ----
#pragma unroll
        for (int ks = 0; ks < 4; ks++) {
            const int k0 = ks * 8;
            unsigned af[2][4];
#pragma unroll
            for (int mi = 0; mi < 2; mi++) {
                int rb = wm * 32 + mi * 16;
                af[mi][0] = As[(rb + gr) * 36 + k0 + tig];
                af[mi][1] = As[(rb + gr + 8) * 36 + k0 + tig];
                af[mi][2] = As[(rb + gr) * 36 + k0 + tig + 4];
                af[mi][3] = As[(rb + gr + 8) * 36 + k0 + tig + 4];
            }
            unsigned bf[8][2];
#pragma unroll
            for (int ni = 0; ni < 8; ni++) {
                int cb = wn * 64 + ni * 8 + gr;
                bf[ni][0] = Bs[(k0 + tig) * 132 + cb];
                bf[ni][1] = Bs[(k0 + tig + 4) * 132 + cb];
            }
#pragma unroll
            for (int mi = 0; mi < 2; mi++)
#pragma unroll
                for (int ni = 0; ni < 8; ni++)
                    mma_tf32(acc[mi][ni], af[mi], bf[ni]);
        }
        __syncthreads();
    }

    // ---- epilogue ----
#pragma unroll
    for (int mi = 0; mi < 2; mi++) {
#pragma unroll
        for (int ni = 0; ni < 8; ni++) {
            int row = r0 + wm * 32 + mi * 16 + gr;
            int col = c0 + wn * 64 + ni * 8 + tig * 2;
#pragma unroll
            for (int half = 0; half < 2; half++) {
                int rr = row + half * 8;
                float x0 = acc[mi][ni][half * 2 + 0];
                float x1 = acc[mi][ni][half * 2 + 1];
                if (EPI == 0) {
                    float b0 = bias[col], b1 = bias[col + 1];
                    float g0 = 1.0f / (1.0f + __expf(-(x0 + b0)));
                    float g1 = 1.0f / (1.0f + __expf(-(x1 + b1)));
                    float2 w = *(const float2*)&g_wavg[b * HV + col];
                    float2 o;
                    o.x = __uint_as_float(f2tf(g0 * w.x));
                    o.y = __uint_as_float(f2tf(g1 * w.y));
                    *(float2*)&Cg[(size_t)rr * 256 + col] = o;
                } else {
                    float2 o;
                    o.x = x0 + bias[col];
                    o.y = x1 + bias[col + 1];
                    *(float2*)&Cg[(size_t)rr * 256 + col] = o;
                }
            }
        }
    }
}

// ---------------- launcher ------------------------------------------------------
extern "C" void kernel_launch(void* const* d_in, const int* in_sizes, int n_in,
                              void* d_out, int out_size) {
    const float* qd = (const float*)d_in[0];
    const float* md = (const float*)d_in[1];
    const float* qm = (const float*)d_in[2];
    const float* qw = (const float*)d_in[3];
    const float* kw = (const float*)d_in[4];
    const float* vw = (const float*)d_in[5];
    const float* gw = (const float*)d_in[6];
    const float* gb = (const float*)d_in[7];
    const float* ow = (const float*)d_in[8];
    const float* ob = (const float*)d_in[9];
    float* out = (float*)d_out;

    float *gated = nullptr, *gwtf = nullptr, *owtf = nullptr;
    cudaGetSymbolAddress((void**)&gated, g_gated);
    cudaGetSymbolAddress((void**)&gwtf, g_gwtf);
    cudaGetSymbolAddress((void**)&owtf, g_owtf);

    cudaFuncSetAttribute(k4_mma<0>, cudaFuncAttributeMaxDynamicSharedMemorySize, K4_SMEM);
    cudaFuncSetAttribute(k4_mma<1>, cudaFuncAttributeMaxDynamicSharedMemorySize, K4_SMEM);

    k0_cvtw<<<256, 256>>>(gw, ow);
    k1_qavg<<<BQ, 256>>>(qd, qm, qw);
    k2_kv_logits<<<dim3(NQ / 128, BQ), 256>>>(md, qm, kw, vw);
    k3_softmax_wavg<<<BQ, 256>>>();
    k4_mma<0><<<dim3((BQ * NQ) / 128, HV / 128), 256, K4_SMEM>>>(qd, gwtf, gb, gated);
    k4_mma<1><<<dim3((BQ * NQ) / 128, OQ / 128), 256, K4_SMEM>>>(gated, owtf, ob, out);
}

// round 8
// speedup vs baseline: 1.7770x; 1.4187x over previous
#include <cuda_runtime.h>
#include <math.h>
#include <stdint.h>

#define BQ 64
#define NQ 2048
#define DQ 256
#define HQ 8
#define KDQ 32
#define VDQ 32
#define OQ 256
#define HV 256

// ---------------- scratch (static device arrays: no allocation) ----------------
__device__ float g_q[BQ * HQ * KDQ];
__device__ float g_v[(size_t)BQ * NQ * VDQ];         // 16 MB
__device__ float g_logits[(size_t)BQ * HQ * NQ];     // 4 MB
__device__ float g_wavg[BQ * HV];
__device__ float g_gated[(size_t)BQ * NQ * HV];      // 128 MB (tf32 patterns)
__device__ float g_gwtf[DQ * HV];
__device__ float g_owtf[HV * OQ];
// reduction scratch
__device__ float g_part1[BQ * 16 * DQ];              // k1 partial masked sums
__device__ float g_part1m[BQ * 16];                  // k1 partial mask sums
__device__ float g_part3[BQ * 16 * HV];              // k3 partial weighted sums
__device__ float g_mx[BQ * HQ];
__device__ float g_is[BQ * HQ];

// ---------------- helpers -------------------------------------------------------
__device__ __forceinline__ unsigned f2tf(float f) {
    unsigned u;
    asm("cvt.rna.tf32.f32 %0, %1;" : "=r"(u) : "f"(f));
    return u;
}
__device__ __forceinline__ uint32_t smem_u32(const void* p) {
    uint32_t a;
    asm("{ .reg .u64 t; cvta.to.shared.u64 t, %1; cvt.u32.u64 %0, t; }" : "=r"(a) : "l"(p));
    return a;
}
__device__ __forceinline__ void cp16(uint32_t saddr, const void* g) {
    asm volatile("cp.async.cg.shared.global [%0], [%1], 16;" :: "r"(saddr), "l"(g) : "memory");
}
__device__ __forceinline__ void cp_commit() {
    asm volatile("cp.async.commit_group;" ::: "memory");
}
template <int N>
__device__ __forceinline__ void cp_wait() {
    asm volatile("cp.async.wait_group %0;" :: "n"(N) : "memory");
}
__device__ __forceinline__ void mma_tf32(float* d, const unsigned* a, const unsigned* b) {
    asm volatile(
        "mma.sync.aligned.m16n8k8.row.col.f32.tf32.tf32.f32 "
        "{%0,%1,%2,%3}, {%4,%5,%6,%7}, {%8,%9}, {%0,%1,%2,%3};\n"
        : "+f"(d[0]), "+f"(d[1]), "+f"(d[2]), "+f"(d[3])
        : "r"(a[0]), "r"(a[1]), "r"(a[2]), "r"(a[3]), "r"(b[0]), "r"(b[1]));
}

// ---------------- K0: weights -> tf32 patterns ----------------------------------
__global__ void k0_cvtw(const float* __restrict__ gw, const float* __restrict__ ow) {
    int i = blockIdx.x * 256 + threadIdx.x;
    g_gwtf[i] = __uint_as_float(f2tf(gw[i]));
    g_owtf[i] = __uint_as_float(f2tf(ow[i]));
}

// ---------------- K1a: partial masked sums over 128-row chunks ------------------
__global__ void k1a(const float* __restrict__ qd, const float* __restrict__ qm) {
    int b = blockIdx.x, ch = blockIdx.y, t = threadIdx.x;
    __shared__ float msk[128];
    int n0 = ch * 128;
    if (t < 128) msk[t] = qm[b * NQ + n0 + t];
    __syncthreads();

    const float* base = qd + ((size_t)b * NQ + n0) * DQ + t;
    float acc = 0.f;
#pragma unroll 8
    for (int r = 0; r < 128; r++) acc += msk[r] * base[(size_t)r * DQ];
    g_part1[(b * 16 + ch) * DQ + t] = acc;

    if (t < 32) {
        float s = 0.f;
        for (int i = t; i < 128; i += 32) s += msk[i];
#pragma unroll
        for (int o = 16; o > 0; o >>= 1) s += __shfl_xor_sync(0xffffffffu, s, o);
        if (t == 0) g_part1m[b * 16 + ch] = s;
    }
}

// ---------------- K1b: reduce + project -----------------------------------------
__global__ void k1b(const float* __restrict__ qw) {
    int b = blockIdx.x, t = threadIdx.x;
    __shared__ float qavg[DQ];
    float s = 0.f, ms = 0.f;
#pragma unroll
    for (int c = 0; c < 16; c++) {
        s += g_part1[(b * 16 + c) * DQ + t];
        ms += g_part1m[b * 16 + c];
    }
    qavg[t] = s / (ms + 1e-10f);
    __syncthreads();

    float r = 0.f;
#pragma unroll 8
    for (int d = 0; d < DQ; d++) r += qavg[d] * qw[d * 256 + t];
    g_q[b * 256 + t] = r * 0.17677669529663687f;
}

// ---------------- K2: k/v via tf32 MMA + logits ---------------------------------
__global__ __launch_bounds__(256) void k2_kv_logits(const float* __restrict__ md,
                                                    const float* __restrict__ qm,
                                                    const float* __restrict__ kw,
                                                    const float* __restrict__ vw) {
    int n0 = blockIdx.x * 128;
    int b  = blockIdx.y;
    int t  = threadIdx.x;
    const int lane = t & 31, wid = t >> 5;
    const int wm = wid >> 1, wn = wid & 1;
    const int gr = lane >> 2, tig = lane & 3;

    __shared__ unsigned As[128 * 36];
    __shared__ unsigned Bs[32 * 68];
    __shared__ float qs[8][32];
    float* Asf = (float*)As;

    float acc[2][4][4];
#pragma unroll
    for (int mi = 0; mi < 2; mi++)
#pragma unroll
        for (int ni = 0; ni < 4; ni++)
#pragma unroll
            for (int j = 0; j < 4; j++) acc[mi][ni][j] = 0.f;

    const float* Abase = md + ((size_t)b * NQ + n0) * DQ;

    float4 a4[4], b4[2];
#pragma unroll
    for (int i = 0; i < 4; i++) {
        int s = t + i * 256;
        int row = s >> 3, c4 = s & 7;
        a4[i] = *(const float4*)(Abase + (size_t)row * DQ + c4 * 4);
    }
#pragma unroll
    for (int i = 0; i < 2; i++) {
        int s = t + i * 256;
        int k = s >> 4, c8 = s & 15;
        b4[i] = (c8 < 8) ? *(const float4*)(kw + k * 32 + c8 * 4)
                         : *(const float4*)(vw + k * 32 + (c8 - 8) * 4);
    }

#pragma unroll 1
    for (int kc = 0; kc < 8; kc++) {
        __syncthreads();
#pragma unroll
        for (int i = 0; i < 4; i++) {
            int s = t + i * 256;
            int row = s >> 3, c4 = s & 7;
            As[row * 36 + c4 * 4 + 0] = f2tf(a4[i].x);
            As[row * 36 + c4 * 4 + 1] = f2tf(a4[i].y);
            As[row * 36 + c4 * 4 + 2] = f2tf(a4[i].z);
            As[row * 36 + c4 * 4 + 3] = f2tf(a4[i].w);
        }
#pragma unroll
        for (int i = 0; i < 2; i++) {
            int s = t + i * 256;
            int k = s >> 4, c8 = s & 15;
            Bs[k * 68 + c8 * 4 + 0] = f2tf(b4[i].x);
            Bs[k * 68 + c8 * 4 + 1] = f2tf(b4[i].y);
            Bs[k * 68 + c8 * 4 + 2] = f2tf(b4[i].z);
            Bs[k * 68 + c8 * 4 + 3] = f2tf(b4[i].w);
        }
        __syncthreads();
        if (kc < 7) {
#pragma unroll
            for (int i = 0; i < 4; i++) {
                int s = t + i * 256;
                int row = s >> 3, c4 = s & 7;
                a4[i] = *(const float4*)(Abase + (size_t)row * DQ + (kc + 1) * 32 + c4 * 4);
            }
#pragma unroll
            for (int i = 0; i < 2; i++) {
                int s = t + i * 256;
                int k = (kc + 1) * 32 + (s >> 4);
                int c8 = s & 15;
                b4[i] = (c8 < 8) ? *(const float4*)(kw + k * 32 + c8 * 4)
                                 : *(const float4*)(vw + k * 32 + (c8 - 8) * 4);
            }
        }
#pragma unroll
        for (int ks = 0; ks < 4; ks++) {
            const int k0 = ks * 8;
            unsigned af[2][4];
#pragma unroll
            for (int mi = 0; mi < 2; mi++) {
                int rb = wm * 32 + mi * 16;
                af[mi][0] = As[(rb + gr) * 36 + k0 + tig];
                af[mi][1] = As[(rb + gr + 8) * 36 + k0 + tig];
                af[mi][2] = As[(rb + gr) * 36 + k0 + tig + 4];
                af[mi][3] = As[(rb + gr + 8) * 36 + k0 + tig + 4];
            }
            unsigned bf[4][2];
#pragma unroll
            for (int ni = 0; ni < 4; ni++) {
                int cb = wn * 32 + ni * 8 + gr;
                bf[ni][0] = Bs[(k0 + tig) * 68 + cb];
                bf[ni][1] = Bs[(k0 + tig + 4) * 68 + cb];
            }
#pragma unroll
            for (int mi = 0; mi < 2; mi++)
#pragma unroll
                for (int ni = 0; ni < 4; ni++)
                    mma_tf32(acc[mi][ni], af[mi], bf[ni]);
        }
    }

    __syncthreads();
    qs[t >> 5][t & 31] = g_q[b * 256 + t];

#pragma unroll
    for (int mi = 0; mi < 2; mi++) {
#pragma unroll
        for (int ni = 0; ni < 4; ni++) {
            int col = wn * 32 + ni * 8 + tig * 2;
#pragma unroll
            for (int half = 0; half < 2; half++) {
                int row = wm * 32 + mi * 16 + gr + half * 8;
                float x0 = acc[mi][ni][half * 2 + 0];
                float x1 = acc[mi][ni][half * 2 + 1];
                if (col < 32) {
                    Asf[row * 33 + col] = x0;
                    Asf[row * 33 + col + 1] = x1;
                } else {
                    g_v[((size_t)b * NQ + n0 + row) * VDQ + (col - 32)] = x0;
                    g_v[((size_t)b * NQ + n0 + row) * VDQ + (col - 31)] = x1;
                }
            }
        }
    }
    __syncthreads();

#pragma unroll
    for (int ii = 0; ii < 4; ii++) {
        int idx = ii * 256 + t;
        int h = idx & 7, n = idx >> 3;
        float s = 0.f;
#pragma unroll
        for (int kd = 0; kd < 32; kd++) s += qs[h][kd] * Asf[n * 33 + kd];
        float maskv = qm[b * NQ + n0 + n];
        g_logits[((size_t)b * HQ + h) * NQ + n0 + n] = s + 1e9f * (maskv - 1.0f);
    }
}

// ---------------- K3a: softmax stats per (b,h) ----------------------------------
__global__ void k3a() {
    int b = blockIdx.x, h = blockIdx.y, t = threadIdx.x;
    const float* lrow = g_logits + ((size_t)b * HQ + h) * NQ;
    __shared__ float red[256];

    float m = -1e30f;
#pragma unroll
    for (int i = 0; i < 8; i++) m = fmaxf(m, lrow[t + i * 256]);
    red[t] = m;
    __syncthreads();
    for (int s = 128; s > 0; s >>= 1) {
        if (t < s) red[t] = fmaxf(red[t], red[t + s]);
        __syncthreads();
    }
    float mx = red[0];
    __syncthreads();

    float s = 0.f;
#pragma unroll
    for (int i = 0; i < 8; i++) s += __expf(lrow[t + i * 256] - mx);
    red[t] = s;
    __syncthreads();
    for (int st = 128; st > 0; st >>= 1) {
        if (t < st) red[t] += red[t + st];
        __syncthreads();
    }
    if (t == 0) {
        g_mx[b * 8 + h] = mx;
        g_is[b * 8 + h] = 1.0f / red[0];
    }
}

// ---------------- K3b: partial weighted sums per 128-row chunk ------------------
__global__ void k3b() {
    int b = blockIdx.x, ch = blockIdx.y, t = threadIdx.x;
    int lane = t & 31, wid = t >> 5;
    __shared__ float vsm[128][33];
    __shared__ float lgs[8][128];
    __shared__ float mxs[8];
    int n0 = ch * 128;

    if (t < 8) mxs[t] = g_mx[b * 8 + t];
#pragma unroll
    for (int i = 0; i < 16; i++) {
        int s = t + i * 256;
        int row = s >> 5, col = s & 31;
        vsm[row][col] = g_v[((size_t)b * NQ + n0 + row) * VDQ + col];
    }
#pragma unroll
    for (int i = 0; i < 4; i++) {
        int s = t + i * 256;
        int hh = s >> 7, n = s & 127;
        lgs[hh][n] = g_logits[((size_t)b * HQ + hh) * NQ + n0 + n];
    }
    __syncthreads();
#pragma unroll
    for (int i = 0; i < 4; i++) {
        int s = t + i * 256;
        int hh = s >> 7, n = s & 127;
        lgs[hh][n] = __expf(lgs[hh][n] - mxs[hh]);
    }
    __syncthreads();

    float acc = 0.f;
#pragma unroll 8
    for (int n = 0; n < 128; n++) acc += lgs[wid][n] * vsm[n][lane];
    g_part3[((b * 16 + ch) * 8 + wid) * 32 + lane] = acc;
}

// ---------------- K3c: reduce partials ------------------------------------------
__global__ void k3c() {
    int b = blockIdx.x, t = threadIdx.x;
    int h = t >> 5, vd = t & 31;
    float s = 0.f;
#pragma unroll
    for (int c = 0; c < 16; c++) s += g_part3[((b * 16 + c) * 8 + h) * 32 + vd];
    g_wavg[b * HV + t] = s * g_is[b * 8 + h];
}

// ---------------- K4: tf32 MMA, cp.async double-buffered -------------------------
#define ST_WORDS 8832
#define ST_BYTES 35328
#define B_WOFF   4608
#define B_BOFF   18432
#define K4_SMEM  (2 * ST_BYTES)

template <int EPI>
__global__ __launch_bounds__(256, 2) void k4_mma(const float* __restrict__ Ag,
                                                 const float* __restrict__ Bg,
                                                 const float* __restrict__ bias,
                                                 float* __restrict__ Cg) {
    extern __shared__ unsigned sm[];
    const uint32_t sb = smem_u32(sm);

    const int r0 = blockIdx.x * 128;
    const int c0 = blockIdx.y * 128;
    const int t = threadIdx.x;
    const int lane = t & 31, wid = t >> 5;
    const int wm = wid >> 1, wn = wid & 1;
    const int gr = lane >> 2, tig = lane & 3;
    const int b = r0 >> 11;

    float acc[2][8][4];
#pragma unroll
    for (int mi = 0; mi < 2; mi++)
#pragma unroll
        for (int ni = 0; ni < 8; ni++)
#pragma unroll
            for (int j = 0; j < 4; j++) acc[mi][ni][j] = 0.f;

    float4 a4[4];

    {
        uint32_t base = sb;
#pragma unroll
        for (int i = 0; i < 4; i++) {
            int s = t + i * 256;
            int k = s >> 5, n4 = s & 31;
            cp16(base + B_BOFF + (uint32_t)k * 528 + n4 * 16,
                 Bg + (size_t)k * 256 + c0 + n4 * 4);
        }
        if (EPI == 1) {
#pragma unroll
            for (int i = 0; i < 4; i++) {
                int s = t + i * 256;
                int row = s >> 3, c4 = s & 7;
                cp16(base + (uint32_t)row * 144 + c4 * 16,
                     Ag + (size_t)(r0 + row) * 256 + c4 * 4);
            }
        }
        cp_commit();
        if (EPI == 0) {
#pragma unroll
            for (int i = 0; i < 4; i++) {
                int s = t + i * 256;
                int row = s >> 3, c4 = s & 7;
                a4[i] = *(const float4*)(Ag + (size_t)(r0 + row) * 256 + c4 * 4);
            }
        }
    }

#pragma unroll 1
    for (int kc = 0; kc < 8; kc++) {
        const int st = kc & 1;
        unsigned* As = sm + st * ST_WORDS;
        unsigned* Bs = As + B_WOFF;

        if (EPI == 0) {
#pragma unroll
            for (int i = 0; i < 4; i++) {
                int s = t + i * 256;
                int row = s >> 3, c4 = s & 7;
                uint4 w;
                w.x = f2tf(a4[i].x); w.y = f2tf(a4[i].y);
                w.z = f2tf(a4[i].z); w.w = f2tf(a4[i].w);
                *(uint4*)((unsigned char*)As + (uint32_t)row * 144 + c4 * 16) = w;
            }
            if (kc < 7) {
#pragma unroll
                for (int i = 0; i < 4; i++) {
                    int s = t + i * 256;
                    int row = s >> 3, c4 = s & 7;
                    a4[i] = *(const float4*)(Ag + (size_t)(r0 + row) * 256 + (kc + 1) * 32 + c4 * 4);
                }
            }
        }

        if (kc < 7) {
            uint32_t base = sb + ((kc + 1) & 1) * ST_BYTES;
#pragma unroll
            for (int i = 0; i < 4; i++) {
                int s = t + i * 256;
                int k = s >> 5, n4 = s & 31;
                cp16(base + B_BOFF + (uint32_t)k * 528 + n4 * 16,
                     Bg + (size_t)((kc + 1) * 32 + k) * 256 + c0 + n4 * 4);
            }
            if (EPI == 1) {
#pragma unroll
                for (int i = 0; i < 4; i++) {
                    int s = t + i * 256;
                    int row = s >> 3, c4 = s & 7;
                    cp16(base + (uint32_t)row * 144 + c4 * 16,
                         Ag + (size_t)(r0 + row) * 256 + (kc + 1) * 32 + c4 * 4);
                }
            }
            cp_commit();
            cp_wait<1>();
        } else {
            cp_wait<0>();
        }
        __syncthreads();

#pragma unroll
        for (int ks = 0; ks < 4; ks++) {
            const int k0 = ks * 8;
            unsigned af[2][4];
#pragma unroll
            for (int mi = 0; mi < 2; mi++) {
                int rb = wm * 32 + mi * 16;
                af[mi][0] = As[(rb + gr) * 36 + k0 + tig];
                af[mi][1] = As[(rb + gr + 8) * 36 + k0 + tig];
                af[mi][2] = As[(rb + gr) * 36 + k0 + tig + 4];
                af[mi][3] = As[(rb + gr + 8) * 36 + k0 + tig + 4];
            }
            unsigned bf[8][2];
#pragma unroll
            for (int ni = 0; ni < 8; ni++) {
                int cb = wn * 64 + ni * 8 + gr;
                bf[ni][0] = Bs[(k0 + tig) * 132 + cb];
                bf[ni][1] = Bs[(k0 + tig + 4) * 132 + cb];
            }
#pragma unroll
            for (int mi = 0; mi < 2; mi++)
#pragma unroll
                for (int ni = 0; ni < 8; ni++)
                    mma_tf32(acc[mi][ni], af[mi], bf[ni]);
        }
        __syncthreads();
    }

#pragma unroll
    for (int mi = 0; mi < 2; mi++) {
#pragma unroll
        for (int ni = 0; ni < 8; ni++) {
            int row = r0 + wm * 32 + mi * 16 + gr;
            int col = c0 + wn * 64 + ni * 8 + tig * 2;
#pragma unroll
            for (int half = 0; half < 2; half++) {
                int rr = row + half * 8;
                float x0 = acc[mi][ni][half * 2 + 0];
                float x1 = acc[mi][ni][half * 2 + 1];
                if (EPI == 0) {
                    float b0 = bias[col], b1 = bias[col + 1];
                    float g0 = 1.0f / (1.0f + __expf(-(x0 + b0)));
                    float g1 = 1.0f / (1.0f + __expf(-(x1 + b1)));
                    float2 w = *(const float2*)&g_wavg[b * HV + col];
                    float2 o;
                    o.x = __uint_as_float(f2tf(g0 * w.x));
                    o.y = __uint_as_float(f2tf(g1 * w.y));
                    *(float2*)&Cg[(size_t)rr * 256 + col] = o;
                } else {
                    float2 o;
                    o.x = x0 + bias[col];
                    o.y = x1 + bias[col + 1];
                    *(float2*)&Cg[(size_t)rr * 256 + col] = o;
                }
            }
        }
    }
}

// ---------------- launcher ------------------------------------------------------
extern "C" void kernel_launch(void* const* d_in, const int* in_sizes, int n_in,
                              void* d_out, int out_size) {
    const float* qd = (const float*)d_in[0];
    const float* md = (const float*)d_in[1];
    const float* qm = (const float*)d_in[2];
    const float* qw = (const float*)d_in[3];
    const float* kw = (const float*)d_in[4];
    const float* vw = (const float*)d_in[5];
    const float* gw = (const float*)d_in[6];
    const float* gb = (const float*)d_in[7];
    const float* ow = (const float*)d_in[8];
    const float* ob = (const float*)d_in[9];
    float* out = (float*)d_out;

    float *gated = nullptr, *gwtf = nullptr, *owtf = nullptr;
    cudaGetSymbolAddress((void**)&gated, g_gated);
    cudaGetSymbolAddress((void**)&gwtf, g_gwtf);
    cudaGetSymbolAddress((void**)&owtf, g_owtf);

    cudaFuncSetAttribute(k4_mma<0>, cudaFuncAttributeMaxDynamicSharedMemorySize, K4_SMEM);
    cudaFuncSetAttribute(k4_mma<1>, cudaFuncAttributeMaxDynamicSharedMemorySize, K4_SMEM);

    k0_cvtw<<<256, 256>>>(gw, ow);
    k1a<<<dim3(BQ, 16), 256>>>(qd, qm);
    k1b<<<BQ, 256>>>(qw);
    k2_kv_logits<<<dim3(NQ / 128, BQ), 256>>>(md, qm, kw, vw);
    k3a<<<dim3(BQ, HQ), 256>>>();
    k3b<<<dim3(BQ, 16), 256>>>();
    k3c<<<BQ, 256>>>();
    k4_mma<0><<<dim3((BQ * NQ) / 128, HV / 128), 256, K4_SMEM>>>(qd, gwtf, gb, gated);
    k4_mma<1><<<dim3((BQ * NQ) / 128, OQ / 128), 256, K4_SMEM>>>(gated, owtf, ob, out);
}